// round 4
// baseline (speedup 1.0000x reference)
#include <cuda_runtime.h>
#include <cstdint>

#define B_Q    2048
#define NOBS   2048
#define PP     15
#define GG     21
#define EE     64
#define NCOL   65536          /* D*D */
#define KK     36
#define KPAD   40             /* 5 k-steps of 8 */
#define NK2    20             /* float2 pairs per row: (k, k+4) interleaved */

#define BM 128                /* batch rows per CTA (MMA M) */
#define BN 128                /* S columns per CTA  (MMA N) */

// coef scratch, pre-packed for the GEMM tile: [b][ks*4+tg] = (coef[k], coef[k+4]),
// k = ks*8+tg, tf32-rounded, zero-padded for k>=36.
__device__ float2 g_coef2[B_Q][NK2];

__device__ __forceinline__ uint32_t f2tf32(float x) {
    uint32_t u;
    asm("cvt.rna.tf32.f32 %0, %1;" : "=r"(u) : "f"(x));
    return u;
}

__device__ __forceinline__ void mma_tf32(float* d, const uint32_t* a, const uint32_t* b) {
    asm volatile(
        "mma.sync.aligned.m16n8k8.row.col.f32.tf32.tf32.f32 "
        "{%0,%1,%2,%3}, {%4,%5,%6,%7}, {%8,%9}, {%0,%1,%2,%3};"
        : "+f"(d[0]), "+f"(d[1]), "+f"(d[2]), "+f"(d[3])
        : "r"(a[0]), "r"(a[1]), "r"(a[2]), "r"(a[3]), "r"(b[0]), "r"(b[1]));
}

// ---------------------------------------------------------------------------
// Kernel 1: warp-per-query 1-NN + alpha mixing -> g_coef2 (packed, tf32)
// ---------------------------------------------------------------------------
__device__ __forceinline__ float coef_k(int k, const float* pd, const float* gd,
                                        const float* sAp, const float* sAg) {
    float s = 0.f;
    if (k < PP) {
#pragma unroll
        for (int q = 0; q < PP; q++) s = fmaf(pd[q], sAp[q * PP + k], s);
    } else if (k < KK) {
        const int g = k - PP;
#pragma unroll
        for (int e = 0; e < EE; e++) s = fmaf(gd[e], sAg[e * GG + g], s);
    }
    return __uint_as_float(f2tf32(s));
}

__global__ __launch_bounds__(256) void nn_coef_kernel(
    const float* __restrict__ positions, const float* __restrict__ obs_pos,
    const float* __restrict__ poly_dic,  const float* __restrict__ graph_dic,
    const float* __restrict__ alpha_poly, const float* __restrict__ alpha_graph)
{
    __shared__ float2 sObs[NOBS];
    __shared__ float  sAp[PP * PP];
    __shared__ float  sAg[EE * GG];

    const int tid = threadIdx.x;
    for (int i = tid; i < NOBS; i += 256) sObs[i] = ((const float2*)obs_pos)[i];
    for (int i = tid; i < PP * PP; i += 256) sAp[i] = alpha_poly[i];
    for (int i = tid; i < EE * GG; i += 256) sAg[i] = alpha_graph[i];
    __syncthreads();

    const int wid = tid >> 5, lid = tid & 31;
    const int b = blockIdx.x * 8 + wid;          // 256 blocks x 8 warps = 2048 queries
    const float px = positions[2 * b];
    const float py = positions[2 * b + 1];

    float bestD = 3.0e38f; int bestJ = 0;
    for (int j = lid; j < NOBS; j += 32) {
        const float dx = px - sObs[j].x;
        const float dy = py - sObs[j].y;
        const float d2 = dx * dx + dy * dy;
        if (d2 < bestD) { bestD = d2; bestJ = j; }
    }
    // exact argmin, first-index tiebreak: pack (d2bits, idx), min-reduce
    unsigned long long key = ((unsigned long long)__float_as_uint(bestD) << 32) | (unsigned)bestJ;
#pragma unroll
    for (int off = 16; off >= 1; off >>= 1) {
        unsigned long long o = __shfl_xor_sync(0xFFFFFFFFu, key, off);
        if (o < key) key = o;
    }
    const int bi = (int)(key & 0xFFFFFFFFu);

    const float* pd = poly_dic + bi * PP;
    const float* gd = graph_dic + bi * EE;
    if (lid < NK2) {
        const int ks = lid >> 2, tg = lid & 3;
        const int k_lo = ks * 8 + tg;
        float2 v;
        v.x = coef_k(k_lo, pd, gd, sAp, sAg);
        v.y = coef_k(k_lo + 4, pd, gd, sAp, sAg);
        g_coef2[b][lid] = v;
    }
}

// ---------------------------------------------------------------------------
// Kernel 2: out[b][c] = sum_k coef[b][k] * S[k][c] via mma.sync tf32.
//   8 warps (4 M-groups x 2 N-groups), warp tile 32x64, 2x8 m16n8k8 frags.
//   S columns are permuted in smem so that the epilogue can use STG.128:
//   within each 64-col warp span, smem slot s <-> global col G with
//     G = (f')*16 + tg*4 + fodd*2 + c01, where s = (2f'+fodd)*8 + tg*2 + c01.
// ---------------------------------------------------------------------------
#define SS_STRIDE 132   /* float2 stride: bank = tg*8 + gr*2, conflict-free */

__global__ __launch_bounds__(256, 2) void opd_kernel(
    const float* __restrict__ S_poly, const float* __restrict__ S_graph,
    float* __restrict__ out)
{
    __shared__ float2 sA2[BM][NK2];          // [row][(ks*4+tg)] = (k, k+4)
    __shared__ float2 sS2[NK2][SS_STRIDE];   // [(ks*4+tg)][perm col] = (k, k+4)

    const int tid = threadIdx.x;
    const int wid = tid >> 5, lid = tid & 31;
    const int gr  = lid >> 2;                 // lane/4
    const int tg  = lid & 3;                  // lane%4
    const int wm  = wid >> 1;                 // M offset 32*wm
    const int wn  = wid & 1;                  // N offset 64*wn

    const int rowBase = blockIdx.x * BM;      // batch rows
    const int colBase = blockIdx.y * BN;      // S columns

    // ---- coef tile: straight float4 copy (pre-packed in kernel 1)
    {
        const float4* gsrc = (const float4*)&g_coef2[rowBase][0];
        float4* sdst = (float4*)&sA2[0][0];
#pragma unroll
        for (int i = tid; i < BM * NK2 / 2; i += 256)     // 1280 float4
            sdst[i] = gsrc[i];
    }
    // ---- S tile: k-pair interleave + column permutation + tf32 round
    for (int i = tid; i < KPAD * BN; i += 256) {
        const int k = i >> 7, g = i & 127;
        float v = 0.f;
        if (k < KK) {
            const float* src = (k < PP) ? (S_poly + (size_t)k * NCOL)
                                        : (S_graph + (size_t)(k - PP) * NCOL);
            v = src[colBase + g];
        }
        const int ks = k >> 3, kk = k & 7;
        const int tgk = kk & 3, hi = kk >> 2;
        // permute within the 64-col half
        const int half = g >> 6, l = g & 63;
        const int fp = l >> 4, rem = l & 15;
        const int ptg = rem >> 2, r2 = rem & 3;
        const int s = half * 64 + (fp * 2 + (r2 >> 1)) * 8 + ptg * 2 + (r2 & 1);
        ((float*)&sS2[ks * 4 + tgk][s])[hi] = __uint_as_float(f2tf32(v));
    }
    __syncthreads();

    float d[2][8][4];
#pragma unroll
    for (int mt = 0; mt < 2; mt++)
#pragma unroll
        for (int f = 0; f < 8; f++)
#pragma unroll
            for (int j = 0; j < 4; j++) d[mt][f][j] = 0.f;

#pragma unroll
    for (int ks = 0; ks < KPAD / 8; ks++) {
        uint32_t a[2][4], bfr[8][2];
#pragma unroll
        for (int mt = 0; mt < 2; mt++) {
            const int r0 = wm * 32 + mt * 16 + gr;
            const float2 p0 = sA2[r0][ks * 4 + tg];       // (k, k+4) for row r0
            const float2 p1 = sA2[r0 + 8][ks * 4 + tg];   // (k, k+4) for row r0+8
            a[mt][0] = __float_as_uint(p0.x);
            a[mt][1] = __float_as_uint(p1.x);
            a[mt][2] = __float_as_uint(p0.y);
            a[mt][3] = __float_as_uint(p1.y);
        }
#pragma unroll
        for (int f = 0; f < 8; f++) {
            const float2 q = sS2[ks * 4 + tg][wn * 64 + f * 8 + gr];
            bfr[f][0] = __float_as_uint(q.x);
            bfr[f][1] = __float_as_uint(q.y);
        }
#pragma unroll
        for (int mt = 0; mt < 2; mt++)
#pragma unroll
            for (int f = 0; f < 8; f++)
                mma_tf32(d[mt][f], a[mt], bfr[f]);
    }

    // ---- epilogue: frag pair (2f',2f'+1) -> 4 consecutive global cols -> STG.128
#pragma unroll
    for (int mt = 0; mt < 2; mt++) {
        const int row0 = rowBase + wm * 32 + mt * 16 + gr;
#pragma unroll
        for (int fp = 0; fp < 4; fp++) {
            const int col = colBase + wn * 64 + fp * 16 + tg * 4;
            *(float4*)&out[(size_t)row0 * NCOL + col] =
                make_float4(d[mt][2 * fp][0], d[mt][2 * fp][1],
                            d[mt][2 * fp + 1][0], d[mt][2 * fp + 1][1]);
            *(float4*)&out[(size_t)(row0 + 8) * NCOL + col] =
                make_float4(d[mt][2 * fp][2], d[mt][2 * fp][3],
                            d[mt][2 * fp + 1][2], d[mt][2 * fp + 1][3]);
        }
    }
}

// ---------------------------------------------------------------------------
extern "C" void kernel_launch(void* const* d_in, const int* in_sizes, int n_in,
                              void* d_out, int out_size)
{
    const float* positions   = (const float*)d_in[0];
    const float* obs_pos     = (const float*)d_in[1];
    const float* poly_dic    = (const float*)d_in[2];
    const float* graph_dic   = (const float*)d_in[3];
    const float* alpha_poly  = (const float*)d_in[4];
    const float* alpha_graph = (const float*)d_in[5];
    const float* S_poly      = (const float*)d_in[6];
    const float* S_graph     = (const float*)d_in[7];
    float* out = (float*)d_out;

    nn_coef_kernel<<<B_Q / 8, 256>>>(positions, obs_pos, poly_dic, graph_dic,
                                     alpha_poly, alpha_graph);

    // grid.x = batch tiles (fast) so 16 CTAs sharing one S tile run adjacently
    dim3 grid(B_Q / BM, NCOL / BN);   // (16, 512)
    opd_kernel<<<grid, 256>>>(S_poly, S_graph, out);
}

// round 5
// speedup vs baseline: 1.6950x; 1.6950x over previous
#include <cuda_runtime.h>
#include <cstdint>

#define B_Q    2048
#define NOBS   2048
#define PP     15
#define GG     21
#define EE     64
#define NCOL   65536          /* D*D */
#define KK     36
#define KPAD   40             /* K padded to 5 k-steps of 8 */

#define BM 128                /* batch rows per CTA (MMA M) */
#define BN 128                /* S columns per CTA  (MMA N) */

// coef scratch: [b][KPAD] (tf32-rounded), cols 36..39 zero
__device__ float g_coef[B_Q * KPAD];

__device__ __forceinline__ uint32_t f2tf32(float x) {
    uint32_t u;
    asm("cvt.rna.tf32.f32 %0, %1;" : "=r"(u) : "f"(x));
    return u;
}

__device__ __forceinline__ void mma_tf32(float* d, const uint32_t* a, const uint32_t* b) {
    asm volatile(
        "mma.sync.aligned.m16n8k8.row.col.f32.tf32.tf32.f32 "
        "{%0,%1,%2,%3}, {%4,%5,%6,%7}, {%8,%9}, {%0,%1,%2,%3};"
        : "+f"(d[0]), "+f"(d[1]), "+f"(d[2]), "+f"(d[3])
        : "r"(a[0]), "r"(a[1]), "r"(a[2]), "r"(a[3]), "r"(b[0]), "r"(b[1]));
}

// ---------------------------------------------------------------------------
// Kernel 1: warp-per-query 1-NN + alpha mixing -> g_coef[b][KPAD] (tf32-rounded)
// (identical to the 160us-best version)
// ---------------------------------------------------------------------------
__global__ __launch_bounds__(256) void nn_coef_kernel(
    const float* __restrict__ positions, const float* __restrict__ obs_pos,
    const float* __restrict__ poly_dic,  const float* __restrict__ graph_dic,
    const float* __restrict__ alpha_poly, const float* __restrict__ alpha_graph)
{
    __shared__ float2 sObs[NOBS];
    __shared__ float  sAp[PP * PP];
    __shared__ float  sAg[EE * GG];

    const int tid = threadIdx.x;
    for (int i = tid; i < NOBS; i += 256) sObs[i] = ((const float2*)obs_pos)[i];
    for (int i = tid; i < PP * PP; i += 256) sAp[i] = alpha_poly[i];
    for (int i = tid; i < EE * GG; i += 256) sAg[i] = alpha_graph[i];
    __syncthreads();

    const int wid = tid >> 5, lid = tid & 31;
    const int b = blockIdx.x * 8 + wid;          // 256 blocks x 8 warps = 2048 queries
    const float px = positions[2 * b];
    const float py = positions[2 * b + 1];

    float bestD = 3.0e38f; int bestJ = 0;
    for (int j = lid; j < NOBS; j += 32) {
        const float dx = px - sObs[j].x;
        const float dy = py - sObs[j].y;
        const float d2 = dx * dx + dy * dy;
        if (d2 < bestD) { bestD = d2; bestJ = j; }
    }
    // exact argmin, first-index tiebreak: pack (d2bits, idx), min-reduce
    unsigned long long key = ((unsigned long long)__float_as_uint(bestD) << 32) | (unsigned)bestJ;
#pragma unroll
    for (int off = 16; off >= 1; off >>= 1) {
        unsigned long long o = __shfl_xor_sync(0xFFFFFFFFu, key, off);
        if (o < key) key = o;
    }
    const int bi = (int)(key & 0xFFFFFFFFu);

    const float* pd = poly_dic + bi * PP;
    const float* gd = graph_dic + bi * EE;
#pragma unroll
    for (int c = lid; c < KPAD; c += 32) {
        float s = 0.f;
        if (c < PP) {
#pragma unroll
            for (int q = 0; q < PP; q++) s = fmaf(pd[q], sAp[q * PP + c], s);
        } else if (c < KK) {
            const int g = c - PP;
#pragma unroll
            for (int e = 0; e < EE; e++) s = fmaf(gd[e], sAg[e * GG + g], s);
        }
        g_coef[b * KPAD + c] = __uint_as_float(f2tf32(s));
    }
}

// ---------------------------------------------------------------------------
// Kernel 2: out[b][c] = sum_k coef[b][k] * S[k][c] via mma.sync tf32.
//   Identical to the 160us version EXCEPT: S columns are permuted inside each
//   64-col warp span at smem-store time so the epilogue writes float4 (STG.128).
//   slot s = (2*fp + b1)*8 + ptg*2 + b0  <->  global l = fp*16 + ptg*4 + 2*b1 + b0
// ---------------------------------------------------------------------------
#define SA_STRIDE 44          /* banks 12*gr+tg : all 32 distinct */
#define SS_STRIDE 136         /* banks 8*tg+gr  : all 32 distinct */

__global__ __launch_bounds__(256, 2) void opd_kernel(
    const float* __restrict__ S_poly, const float* __restrict__ S_graph,
    float* __restrict__ out)
{
    __shared__ float sA[BM][SA_STRIDE];       // coef tile  [row][k]
    __shared__ float sS[KPAD][SS_STRIDE];     // S tile     [k][permuted col]

    const int tid = threadIdx.x;
    const int wid = tid >> 5, lid = tid & 31;
    const int gr  = lid >> 2;                 // lane/4
    const int tg  = lid & 3;                  // lane%4
    const int wm  = wid >> 1;                 // M offset 32*wm
    const int wn  = wid & 1;                  // N offset 64*wn

    const int rowBase = blockIdx.x * BM;      // batch rows
    const int colBase = blockIdx.y * BN;      // S columns

    // ---- load coef tile: 128 rows x 40 floats, float4
#pragma unroll
    for (int i = tid; i < BM * (KPAD / 4); i += 256) {
        const int r = i / (KPAD / 4), q = i % (KPAD / 4);
        const float4 v = *(const float4*)&g_coef[(rowBase + r) * KPAD + q * 4];
        *(float4*)&sA[r][q * 4] = v;
    }
    // ---- load S tile with per-64-col permutation + tf32 round
#pragma unroll
    for (int i = tid; i < KPAD * BN; i += 256) {
        const int k = i >> 7, g = i & 127;
        float v = 0.f;
        if (k < KK) {
            const float* src = (k < PP) ? (S_poly + (size_t)k * NCOL)
                                        : (S_graph + (size_t)(k - PP) * NCOL);
            v = src[colBase + g];
        }
        const int half = g >> 6, l = g & 63;
        const int fp = l >> 4, rem = l & 15;
        const int ptg = rem >> 2, r2 = rem & 3;
        const int s = half * 64 + (fp * 2 + (r2 >> 1)) * 8 + ptg * 2 + (r2 & 1);
        sS[k][s] = __uint_as_float(f2tf32(v));
    }
    __syncthreads();

    float d[2][8][4];
#pragma unroll
    for (int mt = 0; mt < 2; mt++)
#pragma unroll
        for (int f = 0; f < 8; f++)
#pragma unroll
            for (int j = 0; j < 4; j++) d[mt][f][j] = 0.f;

#pragma unroll
    for (int ks = 0; ks < KPAD / 8; ks++) {
        const int k0 = ks * 8;
        uint32_t a[2][4], bfr[8][2];
#pragma unroll
        for (int mt = 0; mt < 2; mt++) {
            const int r0 = wm * 32 + mt * 16 + gr;
            a[mt][0] = __float_as_uint(sA[r0][k0 + tg]);
            a[mt][1] = __float_as_uint(sA[r0 + 8][k0 + tg]);
            a[mt][2] = __float_as_uint(sA[r0][k0 + tg + 4]);
            a[mt][3] = __float_as_uint(sA[r0 + 8][k0 + tg + 4]);
        }
#pragma unroll
        for (int f = 0; f < 8; f++) {
            const int c0 = wn * 64 + f * 8 + gr;
            bfr[f][0] = __float_as_uint(sS[k0 + tg][c0]);
            bfr[f][1] = __float_as_uint(sS[k0 + tg + 4][c0]);
        }
#pragma unroll
        for (int mt = 0; mt < 2; mt++)
#pragma unroll
            for (int f = 0; f < 8; f++)
                mma_tf32(d[mt][f], a[mt], bfr[f]);
    }

    // ---- epilogue: frag pair (2fp, 2fp+1) -> 4 consecutive global cols -> STG.128
#pragma unroll
    for (int mt = 0; mt < 2; mt++) {
        const int row0 = rowBase + wm * 32 + mt * 16 + gr;
#pragma unroll
        for (int fp = 0; fp < 4; fp++) {
            const int col = colBase + wn * 64 + fp * 16 + tg * 4;
            *(float4*)&out[(size_t)row0 * NCOL + col] =
                make_float4(d[mt][2 * fp][0], d[mt][2 * fp][1],
                            d[mt][2 * fp + 1][0], d[mt][2 * fp + 1][1]);
            *(float4*)&out[(size_t)(row0 + 8) * NCOL + col] =
                make_float4(d[mt][2 * fp][2], d[mt][2 * fp][3],
                            d[mt][2 * fp + 1][2], d[mt][2 * fp + 1][3]);
        }
    }
}

// ---------------------------------------------------------------------------
extern "C" void kernel_launch(void* const* d_in, const int* in_sizes, int n_in,
                              void* d_out, int out_size)
{
    const float* positions   = (const float*)d_in[0];
    const float* obs_pos     = (const float*)d_in[1];
    const float* poly_dic    = (const float*)d_in[2];
    const float* graph_dic   = (const float*)d_in[3];
    const float* alpha_poly  = (const float*)d_in[4];
    const float* alpha_graph = (const float*)d_in[5];
    const float* S_poly      = (const float*)d_in[6];
    const float* S_graph     = (const float*)d_in[7];
    float* out = (float*)d_out;

    nn_coef_kernel<<<B_Q / 8, 256>>>(positions, obs_pos, poly_dic, graph_dic,
                                     alpha_poly, alpha_graph);

    // grid.x = batch tiles (fast) so 16 CTAs sharing one S tile run adjacently
    dim3 grid(B_Q / BM, NCOL / BN);   // (16, 512)
    opd_kernel<<<grid, 256>>>(S_poly, S_graph, out);
}

// round 6
// speedup vs baseline: 2.1922x; 1.2933x over previous
#include <cuda_runtime.h>
#include <cstdint>

#define B_Q    2048
#define NOBS   2048
#define PP     15
#define GG     21
#define EE     64
#define NCOL   65536          /* D*D */
#define KK     36
#define KPAD   40             /* K padded to 5 k-steps of 8 */

#define BM 128                /* batch rows per CTA (MMA M) */
#define BN 128                /* S columns per CTA  (MMA N) */

// coef scratch: [b][KPAD] (tf32-rounded), cols 36..39 zero
__device__ float g_coef[B_Q * KPAD];

__device__ __forceinline__ uint32_t f2tf32(float x) {
    uint32_t u;
    asm("cvt.rna.tf32.f32 %0, %1;" : "=r"(u) : "f"(x));
    return u;
}

__device__ __forceinline__ void mma_tf32(float* d, const uint32_t* a,
                                         uint32_t b0, uint32_t b1) {
    asm volatile(
        "mma.sync.aligned.m16n8k8.row.col.f32.tf32.tf32.f32 "
        "{%0,%1,%2,%3}, {%4,%5,%6,%7}, {%8,%9}, {%0,%1,%2,%3};"
        : "+f"(d[0]), "+f"(d[1]), "+f"(d[2]), "+f"(d[3])
        : "r"(a[0]), "r"(a[1]), "r"(a[2]), "r"(a[3]), "r"(b0), "r"(b1));
}

// ---------------------------------------------------------------------------
// Kernel 1: warp-per-query 1-NN + alpha mixing -> g_coef[b][KPAD] (tf32-rounded)
// ---------------------------------------------------------------------------
__global__ __launch_bounds__(256) void nn_coef_kernel(
    const float* __restrict__ positions, const float* __restrict__ obs_pos,
    const float* __restrict__ poly_dic,  const float* __restrict__ graph_dic,
    const float* __restrict__ alpha_poly, const float* __restrict__ alpha_graph)
{
    __shared__ float2 sObs[NOBS];
    __shared__ float  sAp[PP * PP];
    __shared__ float  sAg[EE * GG];

    const int tid = threadIdx.x;
    for (int i = tid; i < NOBS; i += 256) sObs[i] = ((const float2*)obs_pos)[i];
    for (int i = tid; i < PP * PP; i += 256) sAp[i] = alpha_poly[i];
    for (int i = tid; i < EE * GG; i += 256) sAg[i] = alpha_graph[i];
    __syncthreads();

    const int wid = tid >> 5, lid = tid & 31;
    const int b = blockIdx.x * 8 + wid;          // 256 blocks x 8 warps = 2048 queries
    const float px = positions[2 * b];
    const float py = positions[2 * b + 1];

    float bestD = 3.0e38f; int bestJ = 0;
    for (int j = lid; j < NOBS; j += 32) {
        const float dx = px - sObs[j].x;
        const float dy = py - sObs[j].y;
        const float d2 = dx * dx + dy * dy;
        if (d2 < bestD) { bestD = d2; bestJ = j; }
    }
    // exact argmin, first-index tiebreak: pack (d2bits, idx), min-reduce
    unsigned long long key = ((unsigned long long)__float_as_uint(bestD) << 32) | (unsigned)bestJ;
#pragma unroll
    for (int off = 16; off >= 1; off >>= 1) {
        unsigned long long o = __shfl_xor_sync(0xFFFFFFFFu, key, off);
        if (o < key) key = o;
    }
    const int bi = (int)(key & 0xFFFFFFFFu);

    const float* pd = poly_dic + bi * PP;
    const float* gd = graph_dic + bi * EE;
#pragma unroll
    for (int c = lid; c < KPAD; c += 32) {
        float s = 0.f;
        if (c < PP) {
#pragma unroll
            for (int q = 0; q < PP; q++) s = fmaf(pd[q], sAp[q * PP + c], s);
        } else if (c < KK) {
            const int g = c - PP;
#pragma unroll
            for (int e = 0; e < EE; e++) s = fmaf(gd[e], sAg[e * GG + g], s);
        }
        g_coef[b * KPAD + c] = __uint_as_float(f2tf32(s));
    }
}

// ---------------------------------------------------------------------------
// Kernel 2: out[b][c] = sum_k coef[b][k] * S[k][c] via mma.sync tf32.
//   Identical layout/loads/stores to the 146us-profile version; the inner loop
//   consumes B-fragments immediately (2 live regs), and __launch_bounds__(256,3)
//   targets 3 CTAs/SM (reg budget 85) to lift occupancy 16 -> 24 warps/SM.
// ---------------------------------------------------------------------------
#define SA_STRIDE 44          /* banks 12*gr+tg : all 32 distinct */
#define SS_STRIDE 136         /* banks 8*tg+gr  : all 32 distinct */

__global__ __launch_bounds__(256, 3) void opd_kernel(
    const float* __restrict__ S_poly, const float* __restrict__ S_graph,
    float* __restrict__ out)
{
    __shared__ float sA[BM][SA_STRIDE];       // coef tile  [row][k]
    __shared__ float sS[KPAD][SS_STRIDE];     // S tile     [k][col]

    const int tid = threadIdx.x;
    const int wid = tid >> 5, lid = tid & 31;
    const int gr  = lid >> 2;                 // lane/4
    const int tg  = lid & 3;                  // lane%4
    const int wm  = wid >> 1;                 // M offset 32*wm
    const int wn  = wid & 1;                  // N offset 64*wn

    const int rowBase = blockIdx.x * BM;      // batch rows
    const int colBase = blockIdx.y * BN;      // S columns

    // ---- load coef tile: 128 rows x 40 floats, float4
#pragma unroll
    for (int i = tid; i < BM * (KPAD / 4); i += 256) {
        const int r = i / (KPAD / 4), q = i % (KPAD / 4);
        const float4 v = *(const float4*)&g_coef[(rowBase + r) * KPAD + q * 4];
        *(float4*)&sA[r][q * 4] = v;
    }
    // ---- load S tile: rows k<36 from S_poly/S_graph, 36..39 zero; tf32-round
#pragma unroll
    for (int i = tid; i < KPAD * BN; i += 256) {
        const int k = i >> 7, c = i & 127;
        float v = 0.f;
        if (k < KK) {
            const float* src = (k < PP) ? (S_poly + (size_t)k * NCOL)
                                        : (S_graph + (size_t)(k - PP) * NCOL);
            v = src[colBase + c];
        }
        sS[k][c] = __uint_as_float(f2tf32(v));
    }
    __syncthreads();

    float d[2][8][4];
#pragma unroll
    for (int mt = 0; mt < 2; mt++)
#pragma unroll
        for (int f = 0; f < 8; f++)
#pragma unroll
            for (int j = 0; j < 4; j++) d[mt][f][j] = 0.f;

#pragma unroll
    for (int ks = 0; ks < KPAD / 8; ks++) {
        const int k0 = ks * 8;
        uint32_t a[2][4];
#pragma unroll
        for (int mt = 0; mt < 2; mt++) {
            const int r0 = wm * 32 + mt * 16 + gr;
            a[mt][0] = __float_as_uint(sA[r0][k0 + tg]);
            a[mt][1] = __float_as_uint(sA[r0 + 8][k0 + tg]);
            a[mt][2] = __float_as_uint(sA[r0][k0 + tg + 4]);
            a[mt][3] = __float_as_uint(sA[r0 + 8][k0 + tg + 4]);
        }
#pragma unroll
        for (int f = 0; f < 8; f++) {
            const int c0 = wn * 64 + f * 8 + gr;
            const uint32_t b0 = __float_as_uint(sS[k0 + tg][c0]);
            const uint32_t b1 = __float_as_uint(sS[k0 + tg + 4][c0]);
            mma_tf32(d[0][f], a[0], b0, b1);
            mma_tf32(d[1][f], a[1], b0, b1);
        }
    }

    // ---- epilogue: c0,c1 -> (row, col..col+1); c2,c3 -> (row+8, ...)
#pragma unroll
    for (int mt = 0; mt < 2; mt++) {
        const int row0 = rowBase + wm * 32 + mt * 16 + gr;
#pragma unroll
        for (int f = 0; f < 8; f++) {
            const int col = colBase + wn * 64 + f * 8 + tg * 2;
            *(float2*)&out[(size_t)row0 * NCOL + col] =
                make_float2(d[mt][f][0], d[mt][f][1]);
            *(float2*)&out[(size_t)(row0 + 8) * NCOL + col] =
                make_float2(d[mt][f][2], d[mt][f][3]);
        }
    }
}

// ---------------------------------------------------------------------------
extern "C" void kernel_launch(void* const* d_in, const int* in_sizes, int n_in,
                              void* d_out, int out_size)
{
    const float* positions   = (const float*)d_in[0];
    const float* obs_pos     = (const float*)d_in[1];
    const float* poly_dic    = (const float*)d_in[2];
    const float* graph_dic   = (const float*)d_in[3];
    const float* alpha_poly  = (const float*)d_in[4];
    const float* alpha_graph = (const float*)d_in[5];
    const float* S_poly      = (const float*)d_in[6];
    const float* S_graph     = (const float*)d_in[7];
    float* out = (float*)d_out;

    nn_coef_kernel<<<B_Q / 8, 256>>>(positions, obs_pos, poly_dic, graph_dic,
                                     alpha_poly, alpha_graph);

    // grid.x = batch tiles (fast) so 16 CTAs sharing one S tile run adjacently
    dim3 grid(B_Q / BM, NCOL / BN);   // (16, 512)
    opd_kernel<<<grid, 256>>>(S_poly, S_graph, out);
}

// round 8
// speedup vs baseline: 2.8280x; 1.2900x over previous
#include <cuda_runtime.h>
#include <cstdint>

#define B_Q    2048
#define NOBS   2048
#define PP     15
#define GG     21
#define EE     64
#define NCOL   65536          /* D*D */
#define KK     36
#define KPAD   40             /* K padded to 5 k-steps of 8 */

#define BM 128                /* batch rows per CTA (MMA M) */
#define BN 128                /* S columns per CTA  (MMA N) */

// coef scratch: [b][KPAD] (tf32-rounded), cols 36..39 zero
__device__ float g_coef[B_Q * KPAD];

__device__ __forceinline__ uint32_t f2tf32(float x) {
    uint32_t u;
    asm("cvt.rna.tf32.f32 %0, %1;" : "=r"(u) : "f"(x));
    return u;
}

__device__ __forceinline__ void mma_tf32(float* d, const uint32_t* a,
                                         uint32_t b0, uint32_t b1) {
    asm volatile(
        "mma.sync.aligned.m16n8k8.row.col.f32.tf32.tf32.f32 "
        "{%0,%1,%2,%3}, {%4,%5,%6,%7}, {%8,%9}, {%0,%1,%2,%3};"
        : "+f"(d[0]), "+f"(d[1]), "+f"(d[2]), "+f"(d[3])
        : "r"(a[0]), "r"(a[1]), "r"(a[2]), "r"(a[3]), "r"(b0), "r"(b1));
}

// ---------------------------------------------------------------------------
// Kernel 1: warp-per-query 1-NN + alpha mixing -> g_coef[b][KPAD] (tf32-rounded)
// (unchanged from R6)
// ---------------------------------------------------------------------------
__global__ __launch_bounds__(256) void nn_coef_kernel(
    const float* __restrict__ positions, const float* __restrict__ obs_pos,
    const float* __restrict__ poly_dic,  const float* __restrict__ graph_dic,
    const float* __restrict__ alpha_poly, const float* __restrict__ alpha_graph)
{
    __shared__ float2 sObs[NOBS];
    __shared__ float  sAp[PP * PP];
    __shared__ float  sAg[EE * GG];

    const int tid = threadIdx.x;
    for (int i = tid; i < NOBS; i += 256) sObs[i] = ((const float2*)obs_pos)[i];
    for (int i = tid; i < PP * PP; i += 256) sAp[i] = alpha_poly[i];
    for (int i = tid; i < EE * GG; i += 256) sAg[i] = alpha_graph[i];
    __syncthreads();

    const int wid = tid >> 5, lid = tid & 31;
    const int b = blockIdx.x * 8 + wid;          // 256 blocks x 8 warps = 2048 queries
    const float px = positions[2 * b];
    const float py = positions[2 * b + 1];

    float bestD = 3.0e38f; int bestJ = 0;
    for (int j = lid; j < NOBS; j += 32) {
        const float dx = px - sObs[j].x;
        const float dy = py - sObs[j].y;
        const float d2 = dx * dx + dy * dy;
        if (d2 < bestD) { bestD = d2; bestJ = j; }
    }
    // exact argmin, first-index tiebreak: pack (d2bits, idx), min-reduce
    unsigned long long key = ((unsigned long long)__float_as_uint(bestD) << 32) | (unsigned)bestJ;
#pragma unroll
    for (int off = 16; off >= 1; off >>= 1) {
        unsigned long long o = __shfl_xor_sync(0xFFFFFFFFu, key, off);
        if (o < key) key = o;
    }
    const int bi = (int)(key & 0xFFFFFFFFu);

    const float* pd = poly_dic + bi * PP;
    const float* gd = graph_dic + bi * EE;
#pragma unroll
    for (int c = lid; c < KPAD; c += 32) {
        float s = 0.f;
        if (c < PP) {
#pragma unroll
            for (int q = 0; q < PP; q++) s = fmaf(pd[q], sAp[q * PP + c], s);
        } else if (c < KK) {
            const int g = c - PP;
#pragma unroll
            for (int e = 0; e < EE; e++) s = fmaf(gd[e], sAg[e * GG + g], s);
        }
        g_coef[b * KPAD + c] = __uint_as_float(f2tf32(s));
    }
}

// ---------------------------------------------------------------------------
// Kernel 2: out[b][c] = sum_k coef[b][k] * S[k][c] via mma.sync tf32.
//   R6 inner loop (conflict-free scalar fragment loads, occ=3) +
//   R5's column permutation so the epilogue writes float4 (STG.128):
//   slot s = (2*fp + b1)*8 + ptg*2 + b0  <->  global l = fp*16 + ptg*4 + 2*b1 + b0
//   B-frag reads index slots directly (same addresses as R6 -> conflict-free).
// ---------------------------------------------------------------------------
#define SA_STRIDE 44          /* banks 12*gr+tg : all 32 distinct */
#define SS_STRIDE 136         /* banks: slot-perm is within-64 bijective -> distinct */

__global__ __launch_bounds__(256, 3) void opd_kernel(
    const float* __restrict__ S_poly, const float* __restrict__ S_graph,
    float* __restrict__ out)
{
    __shared__ float sA[BM][SA_STRIDE];       // coef tile  [row][k]
    __shared__ float sS[KPAD][SS_STRIDE];     // S tile     [k][permuted col slot]

    const int tid = threadIdx.x;
    const int wid = tid >> 5, lid = tid & 31;
    const int gr  = lid >> 2;                 // lane/4
    const int tg  = lid & 3;                  // lane%4
    const int wm  = wid >> 1;                 // M offset 32*wm
    const int wn  = wid & 1;                  // N offset 64*wn

    const int rowBase = blockIdx.x * BM;      // batch rows
    const int colBase = blockIdx.y * BN;      // S columns

    // ---- load coef tile: 128 rows x 40 floats, float4
#pragma unroll
    for (int i = tid; i < BM * (KPAD / 4); i += 256) {
        const int r = i / (KPAD / 4), q = i % (KPAD / 4);
        const float4 v = *(const float4*)&g_coef[(rowBase + r) * KPAD + q * 4];
        *(float4*)&sA[r][q * 4] = v;
    }
    // ---- load S tile with per-64-col permutation + tf32 round
#pragma unroll
    for (int i = tid; i < KPAD * BN; i += 256) {
        const int k = i >> 7, g = i & 127;
        float v = 0.f;
        if (k < KK) {
            const float* src = (k < PP) ? (S_poly + (size_t)k * NCOL)
                                        : (S_graph + (size_t)(k - PP) * NCOL);
            v = src[colBase + g];
        }
        const int half = g >> 6, l = g & 63;
        const int fp = l >> 4, rem = l & 15;
        const int ptg = rem >> 2, r2 = rem & 3;
        const int s = half * 64 + (fp * 2 + (r2 >> 1)) * 8 + ptg * 2 + (r2 & 1);
        sS[k][s] = __uint_as_float(f2tf32(v));
    }
    __syncthreads();

    float d[2][8][4];
#pragma unroll
    for (int mt = 0; mt < 2; mt++)
#pragma unroll
        for (int f = 0; f < 8; f++)
#pragma unroll
            for (int j = 0; j < 4; j++) d[mt][f][j] = 0.f;

#pragma unroll
    for (int ks = 0; ks < KPAD / 8; ks++) {
        const int k0 = ks * 8;
        uint32_t a[2][4];
#pragma unroll
        for (int mt = 0; mt < 2; mt++) {
            const int r0 = wm * 32 + mt * 16 + gr;
            a[mt][0] = __float_as_uint(sA[r0][k0 + tg]);
            a[mt][1] = __float_as_uint(sA[r0 + 8][k0 + tg]);
            a[mt][2] = __float_as_uint(sA[r0][k0 + tg + 4]);
            a[mt][3] = __float_as_uint(sA[r0 + 8][k0 + tg + 4]);
        }
#pragma unroll
        for (int f = 0; f < 8; f++) {
            const int c0 = wn * 64 + f * 8 + gr;
            const uint32_t b0 = __float_as_uint(sS[k0 + tg][c0]);
            const uint32_t b1 = __float_as_uint(sS[k0 + tg + 4][c0]);
            mma_tf32(d[0][f], a[0], b0, b1);
            mma_tf32(d[1][f], a[1], b0, b1);
        }
    }

    // ---- epilogue: frag pair (2fp, 2fp+1) -> 4 consecutive global cols -> STG.128
#pragma unroll
    for (int mt = 0; mt < 2; mt++) {
        const int row0 = rowBase + wm * 32 + mt * 16 + gr;
#pragma unroll
        for (int fp = 0; fp < 4; fp++) {
            const int col = colBase + wn * 64 + fp * 16 + tg * 4;
            *(float4*)&out[(size_t)row0 * NCOL + col] =
                make_float4(d[mt][2 * fp][0], d[mt][2 * fp][1],
                            d[mt][2 * fp + 1][0], d[mt][2 * fp + 1][1]);
            *(float4*)&out[(size_t)(row0 + 8) * NCOL + col] =
                make_float4(d[mt][2 * fp][2], d[mt][2 * fp][3],
                            d[mt][2 * fp + 1][2], d[mt][2 * fp + 1][3]);
        }
    }
}

// ---------------------------------------------------------------------------
extern "C" void kernel_launch(void* const* d_in, const int* in_sizes, int n_in,
                              void* d_out, int out_size)
{
    const float* positions   = (const float*)d_in[0];
    const float* obs_pos     = (const float*)d_in[1];
    const float* poly_dic    = (const float*)d_in[2];
    const float* graph_dic   = (const float*)d_in[3];
    const float* alpha_poly  = (const float*)d_in[4];
    const float* alpha_graph = (const float*)d_in[5];
    const float* S_poly      = (const float*)d_in[6];
    const float* S_graph     = (const float*)d_in[7];
    float* out = (float*)d_out;

    nn_coef_kernel<<<B_Q / 8, 256>>>(positions, obs_pos, poly_dic, graph_dic,
                                     alpha_poly, alpha_graph);

    // grid.x = batch tiles (fast) so 16 CTAs sharing one S tile run adjacently
    dim3 grid(B_Q / BM, NCOL / BN);   // (16, 512)
    opd_kernel<<<grid, 256>>>(S_poly, S_graph, out);
}